// round 5
// baseline (speedup 1.0000x reference)
#include <cuda_runtime.h>
#include <math.h>

// Problem constants
#define B_  4
#define S_  2048
#define D_  1024
#define F_  4096
#define E_  8
#define T_  (B_*S_)          // 8192 tokens
#define NA_ (T_*2)           // 16384 assignments (top-2)

// GEMM tiling
#define BM 128
#define BN 64
#define BK 16
#define NTHREADS 256

// ---------------------------------------------------------------------------
// Scratch (device globals; no allocations anywhere)
// ---------------------------------------------------------------------------
__device__ int   g_count[E_];
__device__ float g_pacc[E_];
__device__ float g_zacc;
__device__ int   g_tok [E_*T_];
__device__ int   g_slot[E_*T_];
__device__ float g_gate[E_*T_];
__device__ float g_H[(size_t)NA_ * F_];   // SwiGLU hidden, 268 MB
__device__ float g_Y[(size_t)NA_ * D_];   // per-assignment down output, 67 MB

// ---------------------------------------------------------------------------
// 0) zero the per-launch accumulators (graph-replay safe)
// ---------------------------------------------------------------------------
__global__ void init_kernel() {
    int i = threadIdx.x;
    if (i < E_) { g_count[i] = 0; g_pacc[i] = 0.f; }
    if (i == 0) g_zacc = 0.f;
}

// ---------------------------------------------------------------------------
// 1) router: logits, softmax stats, top-2, gather lists
//    1 warp per token, 8 warps per block
// ---------------------------------------------------------------------------
__global__ void router_kernel(const float* __restrict__ x,
                              const float* __restrict__ Wr) {
    int warp = threadIdx.x >> 5;
    int lane = threadIdx.x & 31;
    int t = blockIdx.x * 8 + warp;
    if (t >= T_) return;

    const float* xr = x + (size_t)t * D_;
    float acc[E_];
#pragma unroll
    for (int e = 0; e < E_; e++) acc[e] = 0.f;

    for (int d = lane; d < D_; d += 32) {
        float xv = xr[d];
        const float* w = Wr + d * E_;
#pragma unroll
        for (int e = 0; e < E_; e++) acc[e] += xv * w[e];
    }
#pragma unroll
    for (int off = 16; off; off >>= 1) {
#pragma unroll
        for (int e = 0; e < E_; e++)
            acc[e] += __shfl_xor_sync(0xffffffffu, acc[e], off);
    }

    if (lane == 0) {
        // softmax stats + z-loss
        float mx = acc[0];
#pragma unroll
        for (int e = 1; e < E_; e++) mx = fmaxf(mx, acc[e]);
        float ex[E_], s = 0.f;
#pragma unroll
        for (int e = 0; e < E_; e++) { ex[e] = expf(acc[e] - mx); s += ex[e]; }
        float lse = mx + logf(s);
        atomicAdd(&g_zacc, lse * lse);
        float inv = 1.f / s;
#pragma unroll
        for (int e = 0; e < E_; e++) atomicAdd(&g_pacc[e], ex[e] * inv);

        // top-2 (strict > keeps lowest index on tie, matching lax.top_k)
        int i0 = 0;
#pragma unroll
        for (int e = 1; e < E_; e++) if (acc[e] > acc[i0]) i0 = e;
        int i1 = (i0 == 0) ? 1 : 0;
#pragma unroll
        for (int e = 0; e < E_; e++)
            if (e != i0 && acc[e] > acc[i1]) i1 = e;

        // softmax over the two top logits
        float g0 = 1.f / (1.f + expf(acc[i1] - acc[i0]));
        float g1 = 1.f - g0;

        int p0 = atomicAdd(&g_count[i0], 1);
        g_tok [i0*T_ + p0] = t;
        g_slot[i0*T_ + p0] = 2*t;
        g_gate[i0*T_ + p0] = g0;
        int p1 = atomicAdd(&g_count[i1], 1);
        g_tok [i1*T_ + p1] = t;
        g_slot[i1*T_ + p1] = 2*t + 1;
        g_gate[i1*T_ + p1] = g1;
    }
}

// ---------------------------------------------------------------------------
// 2) up+gate fused GEMM with gathered A rows, SiLU*gate epilogue -> g_H
//    C[i,n] = silu(Xg @ Wup[e])[i,n] * (Xg @ Wgate[e])[i,n]
// ---------------------------------------------------------------------------
__global__ void __launch_bounds__(NTHREADS, 2)
upgate_kernel(const float* __restrict__ x,
              const float* __restrict__ Wup,
              const float* __restrict__ Wgate) {
    const int e  = blockIdx.z;
    const int ne = g_count[e];
    const int m0 = blockIdx.y * BM;
    if (m0 >= ne) return;
    const int n0 = blockIdx.x * BN;

    const float* Bu = Wup   + (size_t)e * D_ * F_;
    const float* Bg = Wgate + (size_t)e * D_ * F_;

    __shared__ __align__(16) float As [BK][BM];
    __shared__ __align__(16) float BsU[BK][BN];
    __shared__ __align__(16) float BsG[BK][BN];

    const int tid = threadIdx.x;

    // A-tile load mapping: 512 float4 slots, 2 per thread
    const float* aptr[2];
    int arow[2], ac4[2];
#pragma unroll
    for (int i = 0; i < 2; i++) {
        int slot = tid + NTHREADS * i;
        int row  = slot >> 2;
        int c4   = slot & 3;
        arow[i] = row; ac4[i] = c4;
        int gr = m0 + row;
        if (gr < ne) {
            int tok = g_tok[e*T_ + gr];
            aptr[i] = x + (size_t)tok * D_ + c4 * 4;
        } else {
            aptr[i] = nullptr;
        }
    }
    // B-tile load mapping: 16x64 floats = 256 float4, 1 per thread per matrix
    const int brow = tid >> 4;     // 0..15 (k)
    const int bc4  = tid & 15;     // 0..15 (n/4)
    const float* bup = Bu + (size_t)brow * F_ + n0 + bc4 * 4;
    const float* bgp = Bg + (size_t)brow * F_ + n0 + bc4 * 4;

    const int tx = tid & 15;       // n micro (x4)
    const int ty = tid >> 4;       // m micro (x8)

    float accU[8][4], accG[8][4];
#pragma unroll
    for (int j = 0; j < 8; j++)
#pragma unroll
        for (int jj = 0; jj < 4; jj++) { accU[j][jj] = 0.f; accG[j][jj] = 0.f; }

    float4 ra[2], rbu, rbg;
    const float4 zero4 = make_float4(0.f, 0.f, 0.f, 0.f);

    // prefetch k-tile 0
#pragma unroll
    for (int i = 0; i < 2; i++)
        ra[i] = aptr[i] ? *(const float4*)(aptr[i]) : zero4;
    rbu = *(const float4*)(bup);
    rbg = *(const float4*)(bgp);

    const int NK = D_ / BK;  // 64
    for (int kt = 0; kt < NK; kt++) {
        __syncthreads();
#pragma unroll
        for (int i = 0; i < 2; i++) {
            As[ac4[i]*4 + 0][arow[i]] = ra[i].x;
            As[ac4[i]*4 + 1][arow[i]] = ra[i].y;
            As[ac4[i]*4 + 2][arow[i]] = ra[i].z;
            As[ac4[i]*4 + 3][arow[i]] = ra[i].w;
        }
        *(float4*)&BsU[brow][bc4*4] = rbu;
        *(float4*)&BsG[brow][bc4*4] = rbg;
        __syncthreads();

        if (kt + 1 < NK) {
            int k0 = (kt + 1) * BK;
#pragma unroll
            for (int i = 0; i < 2; i++)
                ra[i] = aptr[i] ? *(const float4*)(aptr[i] + k0) : zero4;
            rbu = *(const float4*)(bup + (size_t)k0 * F_);
            rbg = *(const float4*)(bgp + (size_t)k0 * F_);
        }

#pragma unroll
        for (int kk = 0; kk < BK; kk++) {
            float a[8];
#pragma unroll
            for (int j = 0; j < 8; j++) a[j] = As[kk][ty*8 + j];
            float4 bu = *(float4*)&BsU[kk][tx*4];
            float4 bg = *(float4*)&BsG[kk][tx*4];
#pragma unroll
            for (int j = 0; j < 8; j++) {
                accU[j][0] += a[j] * bu.x;  accU[j][1] += a[j] * bu.y;
                accU[j][2] += a[j] * bu.z;  accU[j][3] += a[j] * bu.w;
                accG[j][0] += a[j] * bg.x;  accG[j][1] += a[j] * bg.y;
                accG[j][2] += a[j] * bg.z;  accG[j][3] += a[j] * bg.w;
            }
        }
    }

    // epilogue: h = silu(u) * g  -> g_H[slot, n]
#pragma unroll
    for (int j = 0; j < 8; j++) {
        int row = m0 + ty*8 + j;
        if (row < ne) {
            int slot = g_slot[e*T_ + row];
            float* hrow = g_H + (size_t)slot * F_ + n0 + tx*4;
#pragma unroll
            for (int jj = 0; jj < 4; jj++) {
                float u = accU[j][jj];
                float g = accG[j][jj];
                hrow[jj] = (u / (1.f + expf(-u))) * g;
            }
        }
    }
}

// ---------------------------------------------------------------------------
// 3) down GEMM with gathered H rows, gate-scaled epilogue -> g_Y
// ---------------------------------------------------------------------------
__global__ void __launch_bounds__(NTHREADS, 2)
down_kernel(const float* __restrict__ Wdown) {
    const int e  = blockIdx.z;
    const int ne = g_count[e];
    const int m0 = blockIdx.y * BM;
    if (m0 >= ne) return;
    const int n0 = blockIdx.x * BN;

    const float* Bd = Wdown + (size_t)e * F_ * D_;

    __shared__ __align__(16) float As[BK][BM];
    __shared__ __align__(16) float Bs[BK][BN];

    const int tid = threadIdx.x;

    const float* aptr[2];
    int arow[2], ac4[2];
#pragma unroll
    for (int i = 0; i < 2; i++) {
        int slot = tid + NTHREADS * i;
        int row  = slot >> 2;
        int c4   = slot & 3;
        arow[i] = row; ac4[i] = c4;
        int gr = m0 + row;
        if (gr < ne) {
            int hs = g_slot[e*T_ + gr];
            aptr[i] = g_H + (size_t)hs * F_ + c4 * 4;
        } else {
            aptr[i] = nullptr;
        }
    }
    const int brow = tid >> 4;
    const int bc4  = tid & 15;
    const float* bdp = Bd + (size_t)brow * D_ + n0 + bc4 * 4;

    const int tx = tid & 15;
    const int ty = tid >> 4;

    float acc[8][4];
#pragma unroll
    for (int j = 0; j < 8; j++)
#pragma unroll
        for (int jj = 0; jj < 4; jj++) acc[j][jj] = 0.f;

    float4 ra[2], rb;
    const float4 zero4 = make_float4(0.f, 0.f, 0.f, 0.f);

#pragma unroll
    for (int i = 0; i < 2; i++)
        ra[i] = aptr[i] ? *(const float4*)(aptr[i]) : zero4;
    rb = *(const float4*)(bdp);

    const int NK = F_ / BK;  // 256
    for (int kt = 0; kt < NK; kt++) {
        __syncthreads();
#pragma unroll
        for (int i = 0; i < 2; i++) {
            As[ac4[i]*4 + 0][arow[i]] = ra[i].x;
            As[ac4[i]*4 + 1][arow[i]] = ra[i].y;
            As[ac4[i]*4 + 2][arow[i]] = ra[i].z;
            As[ac4[i]*4 + 3][arow[i]] = ra[i].w;
        }
        *(float4*)&Bs[brow][bc4*4] = rb;
        __syncthreads();

        if (kt + 1 < NK) {
            int k0 = (kt + 1) * BK;
#pragma unroll
            for (int i = 0; i < 2; i++)
                ra[i] = aptr[i] ? *(const float4*)(aptr[i] + k0) : zero4;
            rb = *(const float4*)(bdp + (size_t)k0 * D_);
        }

#pragma unroll
        for (int kk = 0; kk < BK; kk++) {
            float a[8];
#pragma unroll
            for (int j = 0; j < 8; j++) a[j] = As[kk][ty*8 + j];
            float4 b = *(float4*)&Bs[kk][tx*4];
#pragma unroll
            for (int j = 0; j < 8; j++) {
                acc[j][0] += a[j] * b.x;  acc[j][1] += a[j] * b.y;
                acc[j][2] += a[j] * b.z;  acc[j][3] += a[j] * b.w;
            }
        }
    }

#pragma unroll
    for (int j = 0; j < 8; j++) {
        int row = m0 + ty*8 + j;
        if (row < ne) {
            int   slot = g_slot[e*T_ + row];
            float gate = g_gate[e*T_ + row];
            float* yrow = g_Y + (size_t)slot * D_ + n0 + tx*4;
#pragma unroll
            for (int jj = 0; jj < 4; jj++)
                yrow[jj] = acc[j][jj] * gate;
        }
    }
}

// ---------------------------------------------------------------------------
// 4) combine the two assignment slots per token -> output
// ---------------------------------------------------------------------------
__global__ void combine_kernel(float* __restrict__ out) {
    int t = blockIdx.x;
    int d = threadIdx.x * 4;
    float4 a = *(const float4*)(g_Y + (size_t)(2*t)     * D_ + d);
    float4 b = *(const float4*)(g_Y + (size_t)(2*t + 1) * D_ + d);
    float4 r = make_float4(a.x + b.x, a.y + b.y, a.z + b.z, a.w + b.w);
    *(float4*)(out + (size_t)t * D_ + d) = r;
}

// ---------------------------------------------------------------------------
// 5) losses + tokens_per_expert into the output tail
// ---------------------------------------------------------------------------
__global__ void finalize_kernel(float* __restrict__ out) {
    int tid = threadIdx.x;
    const float Tf = (float)T_;
    float* tail = out + (size_t)T_ * D_;
    if (tid < E_)
        tail[tid] = (float)g_count[tid] / (Tf * 2.f);
    if (tid == 0) {
        float z = g_zacc / Tf;
        float lb = 0.f;
#pragma unroll
        for (int e = 0; e < E_; e++)
            lb += (g_pacc[e] / Tf) * ((float)g_count[e] / (Tf * 2.f));
        lb *= (float)E_;
        float* s = tail + E_;
        s[0] = z;
        s[1] = z * 0.001f;
        s[2] = lb;
        s[3] = lb * 0.1f;
    }
}

// ---------------------------------------------------------------------------
// launch
// ---------------------------------------------------------------------------
extern "C" void kernel_launch(void* const* d_in, const int* in_sizes, int n_in,
                              void* d_out, int out_size) {
    (void)in_sizes; (void)n_in; (void)out_size;
    const float* x     = (const float*)d_in[0];
    const float* Wr    = (const float*)d_in[1];
    const float* Wup   = (const float*)d_in[2];
    const float* Wgate = (const float*)d_in[3];
    const float* Wdown = (const float*)d_in[4];
    float* out = (float*)d_out;

    init_kernel<<<1, 32>>>();
    router_kernel<<<T_ / 8, 256>>>(x, Wr);
    upgate_kernel<<<dim3(F_ / BN, T_ / BM, E_), NTHREADS>>>(x, Wup, Wgate);
    down_kernel<<<dim3(D_ / BN, T_ / BM, E_), NTHREADS>>>(Wdown);
    combine_kernel<<<T_, 256>>>(out);
    finalize_kernel<<<1, 32>>>(out);
}

// round 6
// speedup vs baseline: 1.0011x; 1.0011x over previous
#include <cuda_runtime.h>
#include <math.h>

// Problem constants
#define B_  4
#define S_  2048
#define D_  1024
#define F_  4096
#define E_  8
#define T_  (B_*S_)          // 8192 tokens
#define NA_ (T_*2)           // 16384 assignments (top-2)

// GEMM tiling
#define BM 128
#define BN 64
#define BK 16
#define NTHREADS 256

// ---------------------------------------------------------------------------
// Scratch (device globals; no allocations anywhere)
// ---------------------------------------------------------------------------
__device__ int   g_count[E_];
__device__ float g_pacc[E_];
__device__ float g_zacc;
__device__ int   g_tok [E_*T_];
__device__ int   g_slot[E_*T_];
__device__ float g_gate[E_*T_];
__device__ float g_H[(size_t)NA_ * F_];   // SwiGLU hidden, 268 MB
__device__ float g_Y[(size_t)NA_ * D_];   // per-assignment down output, 67 MB

// ---------------------------------------------------------------------------
// 0) zero the per-launch accumulators (graph-replay safe)
// ---------------------------------------------------------------------------
__global__ void init_kernel() {
    int i = threadIdx.x;
    if (i < E_) { g_count[i] = 0; g_pacc[i] = 0.f; }
    if (i == 0) g_zacc = 0.f;
}

// ---------------------------------------------------------------------------
// 1) router: logits, softmax stats, top-2, gather lists
//    1 warp per token, 8 warps per block
// ---------------------------------------------------------------------------
__global__ void router_kernel(const float* __restrict__ x,
                              const float* __restrict__ Wr) {
    int warp = threadIdx.x >> 5;
    int lane = threadIdx.x & 31;
    int t = blockIdx.x * 8 + warp;
    if (t >= T_) return;

    const float* xr = x + (size_t)t * D_;
    float acc[E_];
#pragma unroll
    for (int e = 0; e < E_; e++) acc[e] = 0.f;

    for (int d = lane; d < D_; d += 32) {
        float xv = xr[d];
        const float* w = Wr + d * E_;
#pragma unroll
        for (int e = 0; e < E_; e++) acc[e] += xv * w[e];
    }
#pragma unroll
    for (int off = 16; off; off >>= 1) {
#pragma unroll
        for (int e = 0; e < E_; e++)
            acc[e] += __shfl_xor_sync(0xffffffffu, acc[e], off);
    }

    if (lane == 0) {
        // softmax stats + z-loss
        float mx = acc[0];
#pragma unroll
        for (int e = 1; e < E_; e++) mx = fmaxf(mx, acc[e]);
        float ex[E_], s = 0.f;
#pragma unroll
        for (int e = 0; e < E_; e++) { ex[e] = expf(acc[e] - mx); s += ex[e]; }
        float lse = mx + logf(s);
        atomicAdd(&g_zacc, lse * lse);
        float inv = 1.f / s;
#pragma unroll
        for (int e = 0; e < E_; e++) atomicAdd(&g_pacc[e], ex[e] * inv);

        // top-2 (strict > keeps lowest index on tie, matching lax.top_k)
        int i0 = 0;
#pragma unroll
        for (int e = 1; e < E_; e++) if (acc[e] > acc[i0]) i0 = e;
        int i1 = (i0 == 0) ? 1 : 0;
#pragma unroll
        for (int e = 0; e < E_; e++)
            if (e != i0 && acc[e] > acc[i1]) i1 = e;

        // softmax over the two top logits
        float g0 = 1.f / (1.f + expf(acc[i1] - acc[i0]));
        float g1 = 1.f - g0;

        int p0 = atomicAdd(&g_count[i0], 1);
        g_tok [i0*T_ + p0] = t;
        g_slot[i0*T_ + p0] = 2*t;
        g_gate[i0*T_ + p0] = g0;
        int p1 = atomicAdd(&g_count[i1], 1);
        g_tok [i1*T_ + p1] = t;
        g_slot[i1*T_ + p1] = 2*t + 1;
        g_gate[i1*T_ + p1] = g1;
    }
}

// ---------------------------------------------------------------------------
// 2) up+gate fused GEMM with gathered A rows, SiLU*gate epilogue -> g_H
//    C[i,n] = silu(Xg @ Wup[e])[i,n] * (Xg @ Wgate[e])[i,n]
// ---------------------------------------------------------------------------
__global__ void __launch_bounds__(NTHREADS, 2)
upgate_kernel(const float* __restrict__ x,
              const float* __restrict__ Wup,
              const float* __restrict__ Wgate) {
    const int e  = blockIdx.z;
    const int ne = g_count[e];
    const int m0 = blockIdx.y * BM;
    if (m0 >= ne) return;
    const int n0 = blockIdx.x * BN;

    const float* Bu = Wup   + (size_t)e * D_ * F_;
    const float* Bg = Wgate + (size_t)e * D_ * F_;

    __shared__ __align__(16) float As [BK][BM];
    __shared__ __align__(16) float BsU[BK][BN];
    __shared__ __align__(16) float BsG[BK][BN];

    const int tid = threadIdx.x;

    // A-tile load mapping: 512 float4 slots, 2 per thread
    const float* aptr[2];
    int arow[2], ac4[2];
#pragma unroll
    for (int i = 0; i < 2; i++) {
        int slot = tid + NTHREADS * i;
        int row  = slot >> 2;
        int c4   = slot & 3;
        arow[i] = row; ac4[i] = c4;
        int gr = m0 + row;
        if (gr < ne) {
            int tok = g_tok[e*T_ + gr];
            aptr[i] = x + (size_t)tok * D_ + c4 * 4;
        } else {
            aptr[i] = nullptr;
        }
    }
    // B-tile load mapping: 16x64 floats = 256 float4, 1 per thread per matrix
    const int brow = tid >> 4;     // 0..15 (k)
    const int bc4  = tid & 15;     // 0..15 (n/4)
    const float* bup = Bu + (size_t)brow * F_ + n0 + bc4 * 4;
    const float* bgp = Bg + (size_t)brow * F_ + n0 + bc4 * 4;

    const int tx = tid & 15;       // n micro (x4)
    const int ty = tid >> 4;       // m micro (x8)

    float accU[8][4], accG[8][4];
#pragma unroll
    for (int j = 0; j < 8; j++)
#pragma unroll
        for (int jj = 0; jj < 4; jj++) { accU[j][jj] = 0.f; accG[j][jj] = 0.f; }

    float4 ra[2], rbu, rbg;
    const float4 zero4 = make_float4(0.f, 0.f, 0.f, 0.f);

    // prefetch k-tile 0
#pragma unroll
    for (int i = 0; i < 2; i++)
        ra[i] = aptr[i] ? *(const float4*)(aptr[i]) : zero4;
    rbu = *(const float4*)(bup);
    rbg = *(const float4*)(bgp);

    const int NK = D_ / BK;  // 64
    for (int kt = 0; kt < NK; kt++) {
        __syncthreads();
#pragma unroll
        for (int i = 0; i < 2; i++) {
            As[ac4[i]*4 + 0][arow[i]] = ra[i].x;
            As[ac4[i]*4 + 1][arow[i]] = ra[i].y;
            As[ac4[i]*4 + 2][arow[i]] = ra[i].z;
            As[ac4[i]*4 + 3][arow[i]] = ra[i].w;
        }
        *(float4*)&BsU[brow][bc4*4] = rbu;
        *(float4*)&BsG[brow][bc4*4] = rbg;
        __syncthreads();

        if (kt + 1 < NK) {
            int k0 = (kt + 1) * BK;
#pragma unroll
            for (int i = 0; i < 2; i++)
                ra[i] = aptr[i] ? *(const float4*)(aptr[i] + k0) : zero4;
            rbu = *(const float4*)(bup + (size_t)k0 * F_);
            rbg = *(const float4*)(bgp + (size_t)k0 * F_);
        }

#pragma unroll
        for (int kk = 0; kk < BK; kk++) {
            float a[8];
#pragma unroll
            for (int j = 0; j < 8; j++) a[j] = As[kk][ty*8 + j];
            float4 bu = *(float4*)&BsU[kk][tx*4];
            float4 bg = *(float4*)&BsG[kk][tx*4];
#pragma unroll
            for (int j = 0; j < 8; j++) {
                accU[j][0] += a[j] * bu.x;  accU[j][1] += a[j] * bu.y;
                accU[j][2] += a[j] * bu.z;  accU[j][3] += a[j] * bu.w;
                accG[j][0] += a[j] * bg.x;  accG[j][1] += a[j] * bg.y;
                accG[j][2] += a[j] * bg.z;  accG[j][3] += a[j] * bg.w;
            }
        }
    }

    // epilogue: h = silu(u) * g  -> g_H[slot, n]
#pragma unroll
    for (int j = 0; j < 8; j++) {
        int row = m0 + ty*8 + j;
        if (row < ne) {
            int slot = g_slot[e*T_ + row];
            float* hrow = g_H + (size_t)slot * F_ + n0 + tx*4;
#pragma unroll
            for (int jj = 0; jj < 4; jj++) {
                float u = accU[j][jj];
                float g = accG[j][jj];
                hrow[jj] = (u / (1.f + expf(-u))) * g;
            }
        }
    }
}

// ---------------------------------------------------------------------------
// 3) down GEMM with gathered H rows, gate-scaled epilogue -> g_Y
// ---------------------------------------------------------------------------
__global__ void __launch_bounds__(NTHREADS, 2)
down_kernel(const float* __restrict__ Wdown) {
    const int e  = blockIdx.z;
    const int ne = g_count[e];
    const int m0 = blockIdx.y * BM;
    if (m0 >= ne) return;
    const int n0 = blockIdx.x * BN;

    const float* Bd = Wdown + (size_t)e * F_ * D_;

    __shared__ __align__(16) float As[BK][BM];
    __shared__ __align__(16) float Bs[BK][BN];

    const int tid = threadIdx.x;

    const float* aptr[2];
    int arow[2], ac4[2];
#pragma unroll
    for (int i = 0; i < 2; i++) {
        int slot = tid + NTHREADS * i;
        int row  = slot >> 2;
        int c4   = slot & 3;
        arow[i] = row; ac4[i] = c4;
        int gr = m0 + row;
        if (gr < ne) {
            int hs = g_slot[e*T_ + gr];
            aptr[i] = g_H + (size_t)hs * F_ + c4 * 4;
        } else {
            aptr[i] = nullptr;
        }
    }
    const int brow = tid >> 4;
    const int bc4  = tid & 15;
    const float* bdp = Bd + (size_t)brow * D_ + n0 + bc4 * 4;

    const int tx = tid & 15;
    const int ty = tid >> 4;

    float acc[8][4];
#pragma unroll
    for (int j = 0; j < 8; j++)
#pragma unroll
        for (int jj = 0; jj < 4; jj++) acc[j][jj] = 0.f;

    float4 ra[2], rb;
    const float4 zero4 = make_float4(0.f, 0.f, 0.f, 0.f);

#pragma unroll
    for (int i = 0; i < 2; i++)
        ra[i] = aptr[i] ? *(const float4*)(aptr[i]) : zero4;
    rb = *(const float4*)(bdp);

    const int NK = F_ / BK;  // 256
    for (int kt = 0; kt < NK; kt++) {
        __syncthreads();
#pragma unroll
        for (int i = 0; i < 2; i++) {
            As[ac4[i]*4 + 0][arow[i]] = ra[i].x;
            As[ac4[i]*4 + 1][arow[i]] = ra[i].y;
            As[ac4[i]*4 + 2][arow[i]] = ra[i].z;
            As[ac4[i]*4 + 3][arow[i]] = ra[i].w;
        }
        *(float4*)&Bs[brow][bc4*4] = rb;
        __syncthreads();

        if (kt + 1 < NK) {
            int k0 = (kt + 1) * BK;
#pragma unroll
            for (int i = 0; i < 2; i++)
                ra[i] = aptr[i] ? *(const float4*)(aptr[i] + k0) : zero4;
            rb = *(const float4*)(bdp + (size_t)k0 * D_);
        }

#pragma unroll
        for (int kk = 0; kk < BK; kk++) {
            float a[8];
#pragma unroll
            for (int j = 0; j < 8; j++) a[j] = As[kk][ty*8 + j];
            float4 b = *(float4*)&Bs[kk][tx*4];
#pragma unroll
            for (int j = 0; j < 8; j++) {
                acc[j][0] += a[j] * b.x;  acc[j][1] += a[j] * b.y;
                acc[j][2] += a[j] * b.z;  acc[j][3] += a[j] * b.w;
            }
        }
    }

#pragma unroll
    for (int j = 0; j < 8; j++) {
        int row = m0 + ty*8 + j;
        if (row < ne) {
            int   slot = g_slot[e*T_ + row];
            float gate = g_gate[e*T_ + row];
            float* yrow = g_Y + (size_t)slot * D_ + n0 + tx*4;
#pragma unroll
            for (int jj = 0; jj < 4; jj++)
                yrow[jj] = acc[j][jj] * gate;
        }
    }
}

// ---------------------------------------------------------------------------
// 4) combine the two assignment slots per token -> output
// ---------------------------------------------------------------------------
__global__ void combine_kernel(float* __restrict__ out) {
    int t = blockIdx.x;
    int d = threadIdx.x * 4;
    float4 a = *(const float4*)(g_Y + (size_t)(2*t)     * D_ + d);
    float4 b = *(const float4*)(g_Y + (size_t)(2*t + 1) * D_ + d);
    float4 r = make_float4(a.x + b.x, a.y + b.y, a.z + b.z, a.w + b.w);
    *(float4*)(out + (size_t)t * D_ + d) = r;
}

// ---------------------------------------------------------------------------
// 5) losses + tokens_per_expert into the output tail
// ---------------------------------------------------------------------------
__global__ void finalize_kernel(float* __restrict__ out) {
    int tid = threadIdx.x;
    const float Tf = (float)T_;
    float* tail = out + (size_t)T_ * D_;
    if (tid < E_)
        tail[tid] = (float)g_count[tid] / (Tf * 2.f);
    if (tid == 0) {
        float z = g_zacc / Tf;
        float lb = 0.f;
#pragma unroll
        for (int e = 0; e < E_; e++)
            lb += (g_pacc[e] / Tf) * ((float)g_count[e] / (Tf * 2.f));
        lb *= (float)E_;
        float* s = tail + E_;
        s[0] = z;
        s[1] = z * 0.001f;
        s[2] = lb;
        s[3] = lb * 0.1f;
    }
}

// ---------------------------------------------------------------------------
// launch
// ---------------------------------------------------------------------------
extern "C" void kernel_launch(void* const* d_in, const int* in_sizes, int n_in,
                              void* d_out, int out_size) {
    (void)in_sizes; (void)n_in; (void)out_size;
    const float* x     = (const float*)d_in[0];
    const float* Wr    = (const float*)d_in[1];
    const float* Wup   = (const float*)d_in[2];
    const float* Wgate = (const float*)d_in[3];
    const float* Wdown = (const float*)d_in[4];
    float* out = (float*)d_out;

    init_kernel<<<1, 32>>>();
    router_kernel<<<T_ / 8, 256>>>(x, Wr);
    upgate_kernel<<<dim3(F_ / BN, T_ / BM, E_), NTHREADS>>>(x, Wup, Wgate);
    down_kernel<<<dim3(D_ / BN, T_ / BM, E_), NTHREADS>>>(Wdown);
    combine_kernel<<<T_, 256>>>(out);
    finalize_kernel<<<1, 32>>>(out);
}